// round 1
// baseline (speedup 1.0000x reference)
#include <cuda_runtime.h>
#include <math.h>

#define B_SZ   4
#define C_DIM  512
#define N_DIM  512
#define S_DIM  64
#define L_DIM  8192

// Scratch (allocation-free rule: __device__ globals)
__device__ float g_x[(size_t)B_SZ * N_DIM * L_DIM];  // after input projection
__device__ float g_y[(size_t)B_SZ * N_DIM * L_DIM];  // after depthwise conv

// ---------------------------------------------------------------------------
// SGEMM: Cout[b] = A(512x512) * Bg[b](512x8192), row-major, fp32.
// 128x128 block tile, BK=8, 256 threads, 8x8 micro-tile per thread.
// ---------------------------------------------------------------------------
__global__ __launch_bounds__(256) void sgemm128(
    const float* __restrict__ A,      // [512, 512] row-major
    const float* __restrict__ Bg,     // [B][512, 8192]
    float* __restrict__ Cg)           // [B][512, 8192]
{
    __shared__ float As[8][128];
    __shared__ float Bs[8][128];

    const int b = blockIdx.z;
    const float* Bptr = Bg + (size_t)b * C_DIM * L_DIM;
    float*       Cptr = Cg + (size_t)b * N_DIM * L_DIM;

    const int rowBase = blockIdx.y * 128;
    const int colBase = blockIdx.x * 128;
    const int tid = threadIdx.x;
    const int ty = tid >> 4;          // 0..15
    const int tx = tid & 15;          // 0..15
    const int aRow = tid >> 1;        // 0..127
    const int aCol = (tid & 1) * 4;   // 0 or 4
    const int bRow = tid >> 5;        // 0..7
    const int bCol = (tid & 31) * 4;  // 0..124

    float acc[8][8];
#pragma unroll
    for (int i = 0; i < 8; i++)
#pragma unroll
        for (int j = 0; j < 8; j++) acc[i][j] = 0.f;

    for (int k0 = 0; k0 < C_DIM; k0 += 8) {
        float4 av = *(const float4*)(A + (size_t)(rowBase + aRow) * C_DIM + k0 + aCol);
        As[aCol + 0][aRow] = av.x;
        As[aCol + 1][aRow] = av.y;
        As[aCol + 2][aRow] = av.z;
        As[aCol + 3][aRow] = av.w;
        float4 bv = *(const float4*)(Bptr + (size_t)(k0 + bRow) * L_DIM + colBase + bCol);
        *(float4*)&Bs[bRow][bCol] = bv;
        __syncthreads();

#pragma unroll
        for (int k = 0; k < 8; k++) {
            float4 a0 = *(const float4*)&As[k][ty * 8];
            float4 a1 = *(const float4*)&As[k][ty * 8 + 4];
            float4 b0 = *(const float4*)&Bs[k][tx * 8];
            float4 b1 = *(const float4*)&Bs[k][tx * 8 + 4];
            float av8[8] = {a0.x, a0.y, a0.z, a0.w, a1.x, a1.y, a1.z, a1.w};
            float bv8[8] = {b0.x, b0.y, b0.z, b0.w, b1.x, b1.y, b1.z, b1.w};
#pragma unroll
            for (int i = 0; i < 8; i++)
#pragma unroll
                for (int j = 0; j < 8; j++)
                    acc[i][j] = fmaf(av8[i], bv8[j], acc[i][j]);
        }
        __syncthreads();
    }

#pragma unroll
    for (int i = 0; i < 8; i++) {
        float* dst = Cptr + (size_t)(rowBase + ty * 8 + i) * L_DIM + colBase + tx * 8;
        *(float4*)dst       = make_float4(acc[i][0], acc[i][1], acc[i][2], acc[i][3]);
        *(float4*)(dst + 4) = make_float4(acc[i][4], acc[i][5], acc[i][6], acc[i][7]);
    }
}

// ---------------------------------------------------------------------------
// Depthwise long conv as a bank of S=64 complex first-order recurrences.
// K[n,l] = sum_s E[n,s] * Re(lambda^l), lambda = exp(a)*(cos w + i sin w)
// => y[l] = sum_s E * Re(h_s[l]),  h_s[l] = lambda*h_s[l-1] + x[l]
// One block per (n, b); thread s owns one mode.
// ---------------------------------------------------------------------------
#define TL 64
__global__ __launch_bounds__(S_DIM) void ssm_scan(
    const float* __restrict__ X,
    float* __restrict__ Y,
    const float* __restrict__ dtA_real,
    const float* __restrict__ dtA_imag,
    const float* __restrict__ Ew)
{
    const int n = blockIdx.x;
    const int b = blockIdx.y;
    const int s = threadIdx.x;  // 0..63

    __shared__ float xs[TL];
    __shared__ float part[TL][S_DIM + 1];

    const float a = dtA_real[n * S_DIM + s];
    const float w = dtA_imag[n * S_DIM + s];
    const float er = expf(a);
    const float lr = er * cosf(w);
    const float li = er * sinf(w);
    const float e  = Ew[n * S_DIM + s];

    float hr = 0.f, hi = 0.f;
    const float* xp = X + ((size_t)b * N_DIM + n) * L_DIM;
    float*       yp = Y + ((size_t)b * N_DIM + n) * L_DIM;

    for (int l0 = 0; l0 < L_DIM; l0 += TL) {
        xs[s] = xp[l0 + s];     // TL == S_DIM == 64
        __syncthreads();        // also separates prev phase2 reads of `part`

#pragma unroll
        for (int t = 0; t < TL; t++) {
            const float x = xs[t];
            const float nhr = fmaf(lr, hr, fmaf(-li, hi, x));
            const float nhi = fmaf(lr, hi, li * hr);
            hr = nhr;
            hi = nhi;
            part[t][s] = e * hr;
        }
        __syncthreads();

        // thread s reduces time-step t = s over all 64 modes (conflict-free)
        float accv = 0.f;
#pragma unroll
        for (int q = 0; q < S_DIM; q++) accv += part[s][q];
        yp[l0 + s] = accv;
    }
}

// ---------------------------------------------------------------------------
extern "C" void kernel_launch(void* const* d_in, const int* in_sizes, int n_in,
                              void* d_out, int out_size)
{
    const float* inp = (const float*)d_in[0];  // [B, C, L]
    const float* ar  = (const float*)d_in[1];  // [N, S]
    const float* ai  = (const float*)d_in[2];  // [N, S]
    const float* Bm  = (const float*)d_in[3];  // [N, C]
    const float* Cm  = (const float*)d_in[4];  // [C, N]
    const float* E   = (const float*)d_in[5];  // [N, S]
    float* out = (float*)d_out;                // [B, C, L]

    float *xp, *yp;
    cudaGetSymbolAddress((void**)&xp, g_x);
    cudaGetSymbolAddress((void**)&yp, g_y);

    dim3 gg(L_DIM / 128, N_DIM / 128, B_SZ);
    sgemm128<<<gg, 256>>>(Bm, inp, xp);                       // x = B @ input
    ssm_scan<<<dim3(N_DIM, B_SZ), S_DIM>>>(xp, yp, ar, ai, E); // depthwise conv
    sgemm128<<<gg, 256>>>(Cm, yp, out);                       // out = C @ y
}

// round 3
// speedup vs baseline: 1.9886x; 1.9886x over previous
#include <cuda_runtime.h>
#include <cuda_bf16.h>
#include <cstdint>
#include <math.h>

#define B_SZ   4
#define C_DIM  512
#define N_DIM  512
#define S_DIM  64
#define L_DIM  8192

typedef __nv_bfloat16 bf16;

// ---------------------------------------------------------------------------
// Scratch (allocation-free rule: __device__ globals)
// ---------------------------------------------------------------------------
__device__ __align__(128) float g_x  [(size_t)B_SZ * N_DIM * L_DIM];   // gemm1 out (fp32)
__device__ __align__(128) bf16  g_inh[(size_t)B_SZ * C_DIM * L_DIM];
__device__ __align__(128) bf16  g_inl[(size_t)B_SZ * C_DIM * L_DIM];
__device__ __align__(128) bf16  g_yh [(size_t)B_SZ * N_DIM * L_DIM];
__device__ __align__(128) bf16  g_yl [(size_t)B_SZ * N_DIM * L_DIM];
__device__ __align__(128) bf16  g_bh [C_DIM * N_DIM];
__device__ __align__(128) bf16  g_bl [C_DIM * N_DIM];
__device__ __align__(128) bf16  g_ch [C_DIM * N_DIM];
__device__ __align__(128) bf16  g_cl [C_DIM * N_DIM];

// ---------------------------------------------------------------------------
// Helpers (base PTX only: works for compute_103 virtual arch)
// ---------------------------------------------------------------------------
__device__ __forceinline__ uint32_t smem_u32(const void* p) {
    uint32_t a;
    asm("{ .reg .u64 t; cvta.to.shared.u64 t, %1; cvt.u32.u64 %0, t; }" : "=r"(a) : "l"(p));
    return a;
}
__device__ __forceinline__ void cpa16(uint32_t d, const void* s) {
    asm volatile("cp.async.cg.shared.global [%0], [%1], 16;" :: "r"(d), "l"(s));
}
#define CP_COMMIT() asm volatile("cp.async.commit_group;" ::: "memory")
#define CP_WAIT2()  asm volatile("cp.async.wait_group 2;"  ::: "memory")

#define LDSM_X4(r0,r1,r2,r3,addr) \
    asm volatile("ldmatrix.sync.aligned.m8n8.x4.shared.b16 {%0,%1,%2,%3}, [%4];" \
        : "=r"(r0), "=r"(r1), "=r"(r2), "=r"(r3) : "r"(addr))
#define LDSM_X4T(r0,r1,r2,r3,addr) \
    asm volatile("ldmatrix.sync.aligned.m8n8.x4.trans.shared.b16 {%0,%1,%2,%3}, [%4];" \
        : "=r"(r0), "=r"(r1), "=r"(r2), "=r"(r3) : "r"(addr))

#define MMA16816(d, a, b0v, b1v) \
    asm volatile("mma.sync.aligned.m16n8k16.row.col.f32.bf16.bf16.f32 " \
        "{%0,%1,%2,%3}, {%4,%5,%6,%7}, {%8,%9}, {%0,%1,%2,%3};" \
        : "+f"((d)[0]), "+f"((d)[1]), "+f"((d)[2]), "+f"((d)[3]) \
        : "r"((a)[0]), "r"((a)[1]), "r"((a)[2]), "r"((a)[3]), "r"(b0v), "r"(b1v))

// ---------------------------------------------------------------------------
// fp32 -> bf16 hi/lo split (pre-pass)
// ---------------------------------------------------------------------------
__global__ __launch_bounds__(256) void split_fp32(
    const float* __restrict__ src, bf16* __restrict__ hi, bf16* __restrict__ lo, int n)
{
    int i = (blockIdx.x * 256 + threadIdx.x) * 4;
    if (i >= n) return;
    float4 v = *(const float4*)(src + i);
    bf16 h0 = __float2bfloat16_rn(v.x), h1 = __float2bfloat16_rn(v.y);
    bf16 h2 = __float2bfloat16_rn(v.z), h3 = __float2bfloat16_rn(v.w);
    bf16 l0 = __float2bfloat16_rn(v.x - __bfloat162float(h0));
    bf16 l1 = __float2bfloat16_rn(v.y - __bfloat162float(h1));
    bf16 l2 = __float2bfloat16_rn(v.z - __bfloat162float(h2));
    bf16 l3 = __float2bfloat16_rn(v.w - __bfloat162float(h3));
    ((__nv_bfloat162*)(hi + i))[0] = __nv_bfloat162(h0, h1);
    ((__nv_bfloat162*)(hi + i))[1] = __nv_bfloat162(h2, h3);
    ((__nv_bfloat162*)(lo + i))[0] = __nv_bfloat162(l0, l1);
    ((__nv_bfloat162*)(lo + i))[1] = __nv_bfloat162(l2, l3);
}

// ---------------------------------------------------------------------------
// HMMA GEMM: Out[b] = W(512x512) @ X[b](512x8192), fp32 via 3-term bf16 split.
// CTA 128x128, BK=32, 4-stage cp.async pipeline, 8 warps (64x32 warp tiles).
// K loop runs 3 virtual segments: (Ah,Bh), (Ah,Bl), (Al,Bh).
// SMEM/stage: A [128 m][32 k] bf16, row stride 80B (pad) = 10240B
//             B [32 k][128 n] bf16, rows 256B with 16B XOR swizzle = 8192B
// ---------------------------------------------------------------------------
#define STAGE  18432
#define A_BYTES 10240
#define NCHUNK 48          // 3 segments x (512/32)
#define GEMM_SMEM (4 * STAGE)

__global__ __launch_bounds__(256, 2) void hgemm(
    const bf16* __restrict__ Ah, const bf16* __restrict__ Al,
    const bf16* __restrict__ Bh0, const bf16* __restrict__ Bl0,
    float* __restrict__ Out)
{
    extern __shared__ char smem[];
    const uint32_t sb = smem_u32(smem);
    const int tid  = threadIdx.x;
    const int lane = tid & 31, wid = tid >> 5;
    const int n0 = blockIdx.x * 128;
    const int m0 = blockIdx.y * 128;
    const bf16* Bh = Bh0 + (size_t)blockIdx.z * C_DIM * L_DIM;
    const bf16* Bl = Bl0 + (size_t)blockIdx.z * C_DIM * L_DIM;
    float* Ob = Out + (size_t)blockIdx.z * N_DIM * L_DIM;

    // load mapping: A tile 512 chunks (m=q/4, c=q%4), B tile 512 chunks (k=q/16, c=q%16)
    const int am = tid >> 2, ac = tid & 3;
    const int bk = tid >> 4, bc = tid & 15;

    auto load_stage = [&](int cl, int st) {
        if (cl < NCHUNK) {
            const bf16* As = (cl < 32) ? Ah : Al;
            const bf16* Bs = (cl >= 16 && cl < 32) ? Bl : Bh;
            const int k0 = (cl & 15) << 5;
            const uint32_t s0 = sb + (uint32_t)st * STAGE;
            cpa16(s0 + am * 80 + ac * 16,
                  As + (size_t)(m0 + am) * C_DIM + k0 + ac * 8);
            cpa16(s0 + (am + 64) * 80 + ac * 16,
                  As + (size_t)(m0 + am + 64) * C_DIM + k0 + ac * 8);
            {
                int c1 = (bc & 8) | ((bc ^ (bk & 7)) & 7);
                cpa16(s0 + A_BYTES + bk * 256 + c1 * 16,
                      Bs + (size_t)(k0 + bk) * L_DIM + n0 + bc * 8);
                int k2 = bk + 16;
                int c2 = (bc & 8) | ((bc ^ (k2 & 7)) & 7);
                cpa16(s0 + A_BYTES + k2 * 256 + c2 * 16,
                      Bs + (size_t)(k0 + k2) * L_DIM + n0 + bc * 8);
            }
        }
        CP_COMMIT();
    };

    // per-warp operand address bases
    const int wm = (wid >> 2) * 64;      // warp m offset (0 / 64)
    const int wn = (wid & 3) * 32;       // warp n offset (0/32/64/96)
    const uint32_t a_base = (uint32_t)(wm + (lane & 15)) * 80 + ((lane >> 4) * 16);
    uint32_t b_off[2];
#pragma unroll
    for (int nt = 0; nt < 2; nt++) {
        int g  = (wn >> 3) + nt * 2 + (lane >> 4);
        int gp = (g & 8) | ((g ^ (lane & 7)) & 7);
        b_off[nt] = (uint32_t)(lane & 15) * 256 + gp * 16;
    }

    float acc[4][4][4];
#pragma unroll
    for (int mt = 0; mt < 4; mt++)
#pragma unroll
        for (int j = 0; j < 4; j++)
#pragma unroll
            for (int r = 0; r < 4; r++) acc[mt][j][r] = 0.f;

    load_stage(0, 0); load_stage(1, 1); load_stage(2, 2);

    for (int c = 0; c < NCHUNK; c++) {
        CP_WAIT2();
        __syncthreads();
        load_stage(c + 3, (c + 3) & 3);

        const uint32_t Abase = sb + (uint32_t)(c & 3) * STAGE;
        const uint32_t Bbase = Abase + A_BYTES;
#pragma unroll
        for (int kh = 0; kh < 2; kh++) {
            uint32_t a[4][4], b[2][4];
#pragma unroll
            for (int mt = 0; mt < 4; mt++)
                LDSM_X4(a[mt][0], a[mt][1], a[mt][2], a[mt][3],
                        Abase + a_base + mt * (16 * 80) + kh * 32);
#pragma unroll
            for (int nt = 0; nt < 2; nt++)
                LDSM_X4T(b[nt][0], b[nt][1], b[nt][2], b[nt][3],
                         Bbase + b_off[nt] + kh * 4096);
#pragma unroll
            for (int mt = 0; mt < 4; mt++) {
                MMA16816(acc[mt][0], a[mt], b[0][0], b[0][1]);
                MMA16816(acc[mt][1], a[mt], b[0][2], b[0][3]);
                MMA16816(acc[mt][2], a[mt], b[1][0], b[1][1]);
                MMA16816(acc[mt][3], a[mt], b[1][2], b[1][3]);
            }
        }
    }

    // epilogue: d-frag (row = lane/4 (+8), col = 2*(lane%4) (+1))
    const int er = lane >> 2, ec = (lane & 3) * 2;
#pragma unroll
    for (int mt = 0; mt < 4; mt++) {
#pragma unroll
        for (int j = 0; j < 4; j++) {
            size_t base = (size_t)(m0 + wm + mt * 16 + er) * L_DIM + (n0 + wn + j * 8 + ec);
            *(float2*)&Ob[base]             = make_float2(acc[mt][j][0], acc[mt][j][1]);
            *(float2*)&Ob[base + 8 * L_DIM] = make_float2(acc[mt][j][2], acc[mt][j][3]);
        }
    }
}

// ---------------------------------------------------------------------------
// Depthwise conv as S=64 complex first-order recurrences.
// One warp per (b,n) chain; lane owns 2 modes. Emits bf16 hi/lo split of y.
// ---------------------------------------------------------------------------
__global__ __launch_bounds__(128) void ssm_scan(
    const float* __restrict__ X,
    bf16* __restrict__ Yh, bf16* __restrict__ Yl,
    const float* __restrict__ Ar, const float* __restrict__ Ai,
    const float* __restrict__ Ew)
{
    const int lane = threadIdx.x;           // 0..31
    const int w = threadIdx.y;              // 0..3
    const int chain = blockIdx.x * 4 + w;   // b*512 + n
    const int n = chain & (N_DIM - 1);

    __shared__ float xs[4][32];
    __shared__ float part[4][32][33];       // stride 33 -> conflict-free transpose

    const int s0 = n * S_DIM + lane * 2;
    float2 av = *(const float2*)&Ar[s0];
    float2 wv = *(const float2*)&Ai[s0];
    float2 ev = *(const float2*)&Ew[s0];
    const float er0 = expf(av.x), er1 = expf(av.y);
    const float lr0 = er0 * cosf(wv.x), lr1 = er1 * cosf(wv.y);
    const float li0 = er0 * sinf(wv.x), li1 = er1 * sinf(wv.y);
    const float e0 = ev.x, e1 = ev.y;

    float hr0 = 0.f, hi0 = 0.f, hr1 = 0.f, hi1 = 0.f;
    const float* xp = X + (size_t)chain * L_DIM;
    bf16* yhp = Yh + (size_t)chain * L_DIM;
    bf16* ylp = Yl + (size_t)chain * L_DIM;

    for (int l0 = 0; l0 < L_DIM; l0 += 32) {
        xs[w][lane] = xp[l0 + lane];
        __syncwarp();
#pragma unroll
        for (int t = 0; t < 32; t++) {
            const float x = xs[w][t];
            float t0 = fmaf(-li0, hi0, x);
            float u0 = fmaf(lr0, hi0, li0 * hr0);
            hr0 = fmaf(lr0, hr0, t0); hi0 = u0;
            float t1 = fmaf(-li1, hi1, x);
            float u1 = fmaf(lr1, hi1, li1 * hr1);
            hr1 = fmaf(lr1, hr1, t1); hi1 = u1;
            part[w][t][lane] = fmaf(e0, hr0, e1 * hr1);
        }
        __syncwarp();
        float acc = 0.f;
#pragma unroll
        for (int q = 0; q < 32; q++) acc += part[w][lane][q];
        bf16 h = __float2bfloat16_rn(acc);
        yhp[l0 + lane] = h;
        ylp[l0 + lane] = __float2bfloat16_rn(acc - __bfloat162float(h));
        __syncwarp();
    }
}

// ---------------------------------------------------------------------------
extern "C" void kernel_launch(void* const* d_in, const int* in_sizes, int n_in,
                              void* d_out, int out_size)
{
    const float* inp = (const float*)d_in[0];  // [B, C, L]
    const float* ar  = (const float*)d_in[1];  // [N, S]
    const float* ai  = (const float*)d_in[2];  // [N, S]
    const float* Bm  = (const float*)d_in[3];  // [N, C]
    const float* Cm  = (const float*)d_in[4];  // [C, N]
    const float* E   = (const float*)d_in[5];  // [N, S]
    float* out = (float*)d_out;                // [B, C, L]

    float *xp;  bf16 *inh, *inl, *yh, *yl, *bh, *bl, *ch, *cl;
    cudaGetSymbolAddress((void**)&xp,  g_x);
    cudaGetSymbolAddress((void**)&inh, g_inh);
    cudaGetSymbolAddress((void**)&inl, g_inl);
    cudaGetSymbolAddress((void**)&yh,  g_yh);
    cudaGetSymbolAddress((void**)&yl,  g_yl);
    cudaGetSymbolAddress((void**)&bh,  g_bh);
    cudaGetSymbolAddress((void**)&bl,  g_bl);
    cudaGetSymbolAddress((void**)&ch,  g_ch);
    cudaGetSymbolAddress((void**)&cl,  g_cl);

    cudaFuncSetAttribute(hgemm, cudaFuncAttributeMaxDynamicSharedMemorySize, GEMM_SMEM);

    const int n_in_elems = B_SZ * C_DIM * L_DIM;
    const int n_w = C_DIM * N_DIM;

    split_fp32<<<n_in_elems / 1024, 256>>>(inp, inh, inl, n_in_elems);
    split_fp32<<<n_w / 1024, 256>>>(Bm, bh, bl, n_w);
    split_fp32<<<n_w / 1024, 256>>>(Cm, ch, cl, n_w);

    dim3 gg(L_DIM / 128, N_DIM / 128, B_SZ);
    hgemm<<<gg, 256, GEMM_SMEM>>>(bh, bl, inh, inl, xp);            // x = B @ input
    ssm_scan<<<(B_SZ * N_DIM) / 4, dim3(32, 4)>>>(xp, yh, yl, ar, ai, E);
    hgemm<<<gg, 256, GEMM_SMEM>>>(ch, cl, yh, yl, out);             // out = C @ y
}